// round 13
// baseline (speedup 1.0000x reference)
#include <cuda_runtime.h>
#include <cuda_fp16.h>
#include <mma.h>
#include <cstdint>

using namespace nvcuda;

static constexpr int B_    = 1024;
static constexpr int NNODE = 10;
static constexpr int FIN   = 2048;
static constexpr int FOUT  = 128;
static constexpr int NH    = 8;
static constexpr int HID   = 128;
static constexpr int M1    = B_ * NNODE;      // 10240 rows
static constexpr int NCAT  = 2048;            // 8 heads * 2 halves * 128

// Scratch (static device arrays: allocation-free per harness rules).
// NOTE: these are referenced ONLY inside device code — passing a __device__
// global as a host-side kernel argument is UB (host shadow address) and was
// the cause of the R8/R9/R11 128MiB guard trips.
__device__ __half g_emb[(size_t)M1 * FOUT];                 // 2.6 MB
__device__ __half g_W1h[(size_t)NH * 2 * 128 * 136];        // 0.56 MB, padded stride 136
__device__ float  g_AC [(size_t)M1 * NCAT];                 // 84 MB (L2-resident working set)

// ---------------------------------------------------------------------------
// Pack W1 (f32 [8][256][128]) -> g_W1h (f16 [8][2][128][136], cols 128..135=0)
// R7-proven scalar version.
// ---------------------------------------------------------------------------
__global__ void __launch_bounds__(256) w1pack_kernel(const float* __restrict__ W1)
{
    int idx = blockIdx.x * 256 + threadIdx.x;               // over 8*2*128*136
    if (idx >= NH*2*128*136) return;
    int c   = idx % 136;
    int row = idx / 136;                                    // (h*2+s)*128 + r
    __half v = __float2half(0.0f);
    if (c < 128){
        v = __float2half(W1[(size_t)row * HID + c]);
    }
    g_W1h[idx] = v;
}

// ---------------------------------------------------------------------------
// GEMM1: emb[10240,128] = X[10240,2048] @ Wp[2048,128] + bp   (f16 in, f32 acc)
// Unchanged (R6/R7 proven, ~49us). Block 64x128, BK=64, 8 warps, double buffer.
// ---------------------------------------------------------------------------
static constexpr int G1_SA_STR  = 72;
static constexpr int G1_SB_STR  = 136;
static constexpr int G1_SA_BUF  = 64 * G1_SA_STR;
static constexpr int G1_SB_BUF  = 64 * G1_SB_STR;
static constexpr int G1_SMEM    = 2*G1_SA_BUF*2 + 2*G1_SB_BUF*2;  // 53248 B

__global__ void __launch_bounds__(256) gemm1_kernel(const float* __restrict__ X,
                                                    const float* __restrict__ Wp,
                                                    const float* __restrict__ bp)
{
    extern __shared__ __align__(16) char smem_raw[];
    __half* sA = (__half*)smem_raw;
    __half* sB = (__half*)(smem_raw + 2*G1_SA_BUF*2);

    const int t    = threadIdx.x;
    const int m0   = blockIdx.x * 64;
    const int warp = t >> 5;
    const int wm   = warp >> 2;
    const int wn   = warp & 3;

    wmma::fragment<wmma::accumulator,16,16,16,float> acc[2][2];
    #pragma unroll
    for (int i=0;i<2;i++)
        #pragma unroll
        for (int j=0;j<2;j++) wmma::fill_fragment(acc[i][j], 0.0f);

    float4 pa[4], pb[8];
    #pragma unroll
    for (int i=0;i<4;i++){ int idx=t+i*256; int r=idx>>4, c=(idx&15)<<2;
        pa[i] = *(const float4*)(X + (size_t)(m0+r)*FIN + c); }
    #pragma unroll
    for (int i=0;i<8;i++){ int idx=t+i*256; int r=idx>>5, c=(idx&31)<<2;
        pb[i] = *(const float4*)(Wp + (size_t)r*FOUT + c); }

    auto store_tiles = [&](int buf){
        __half* a = sA + buf*G1_SA_BUF;
        __half* b = sB + buf*G1_SB_BUF;
        #pragma unroll
        for (int i=0;i<4;i++){ int idx=t+i*256; int r=idx>>4, c=(idx&15)<<2;
            __half2 h0 = __floats2half2_rn(pa[i].x, pa[i].y);
            __half2 h1 = __floats2half2_rn(pa[i].z, pa[i].w);
            __half2* p = (__half2*)(a + r*G1_SA_STR + c);
            p[0] = h0; p[1] = h1; }
        #pragma unroll
        for (int i=0;i<8;i++){ int idx=t+i*256; int r=idx>>5, c=(idx&31)<<2;
            __half2 h0 = __floats2half2_rn(pb[i].x, pb[i].y);
            __half2 h1 = __floats2half2_rn(pb[i].z, pb[i].w);
            __half2* p = (__half2*)(b + r*G1_SB_STR + c);
            p[0] = h0; p[1] = h1; }
    };

    store_tiles(0);
    __syncthreads();

    int buf = 0;
    for (int k0 = 0; k0 < FIN; k0 += 64)
    {
        const int kn = k0 + 64;
        if (kn < FIN){
            #pragma unroll
            for (int i=0;i<4;i++){ int idx=t+i*256; int r=idx>>4, c=(idx&15)<<2;
                pa[i] = *(const float4*)(X + (size_t)(m0+r)*FIN + kn + c); }
            #pragma unroll
            for (int i=0;i<8;i++){ int idx=t+i*256; int r=idx>>5, c=(idx&31)<<2;
                pb[i] = *(const float4*)(Wp + (size_t)(kn+r)*FOUT + c); }
        }

        const __half* a = sA + buf*G1_SA_BUF;
        const __half* b = sB + buf*G1_SB_BUF;
        #pragma unroll
        for (int kk=0; kk<4; kk++){
            wmma::fragment<wmma::matrix_a,16,16,16,__half,wmma::row_major> af[2];
            wmma::fragment<wmma::matrix_b,16,16,16,__half,wmma::row_major> bf[2];
            #pragma unroll
            for (int i=0;i<2;i++)
                wmma::load_matrix_sync(af[i], a + (wm*32 + i*16)*G1_SA_STR + kk*16, G1_SA_STR);
            #pragma unroll
            for (int j=0;j<2;j++)
                wmma::load_matrix_sync(bf[j], b + (kk*16)*G1_SB_STR + wn*32 + j*16, G1_SB_STR);
            #pragma unroll
            for (int i=0;i<2;i++)
                #pragma unroll
                for (int j=0;j<2;j++)
                    wmma::mma_sync(acc[i][j], af[i], bf[j], acc[i][j]);
        }

        if (kn < FIN) store_tiles(buf ^ 1);
        __syncthreads();
        buf ^= 1;
    }

    float* se = (float*)smem_raw;
    #pragma unroll
    for (int i=0;i<2;i++)
        #pragma unroll
        for (int j=0;j<2;j++)
            wmma::store_matrix_sync(se + (wm*32+i*16)*128 + wn*32 + j*16, acc[i][j], 128, wmma::mem_row_major);
    __syncthreads();
    #pragma unroll
    for (int i=0;i<8;i++){
        int idx = t + i*256;
        int r = idx >> 5;
        int c = (idx & 31) << 2;
        float4 v  = *(float4*)(se + r*128 + c);
        float4 bb = *(const float4*)(bp + c);
        __half2 h0 = __floats2half2_rn(v.x + bb.x, v.y + bb.y);
        __half2 h1 = __floats2half2_rn(v.z + bb.z, v.w + bb.w);
        __half2* p = (__half2*)(g_emb + (size_t)(m0+r)*FOUT + c);
        p[0] = h0; p[1] = h1;
    }
}

// ---------------------------------------------------------------------------
// GEMM2: g_AC[10240,2048] = emb @ Wcat (+ b1 on A-halves), f16 in / f32 out.
// g_AC accessed as a device global (NOT a kernel argument).
// Column tile nt (0..15): B slab = g_W1h + nt*128*136  (rows = k, padded f16).
// Block 128x128, 512 threads, 16 warps (warp tile 32x32).
// smem: sE f16[128][136] + sB f16[128][136] = 69632 B.
// ---------------------------------------------------------------------------
static constexpr int G2_STR  = 136;
static constexpr int G2_SMEM = 2 * 128 * G2_STR * 2;   // 69632 B

__global__ void __launch_bounds__(512) gemm2_kernel(const float* __restrict__ b1)
{
    extern __shared__ __align__(16) char smem_raw[];
    __half* sE = (__half*)smem_raw;                       // [128][136]
    __half* sB = (__half*)(smem_raw + 128*G2_STR*2);      // [128][136]

    const int t    = threadIdx.x;
    const int m0   = blockIdx.x * 128;
    const int nt   = blockIdx.y;                          // 0..15
    const int warp = t >> 5;
    const int wm   = warp & 3;       // row tile of 32
    const int wn   = warp >> 2;      // col tile of 32

    {
        const __half* src = g_emb + (size_t)m0*FOUT;
        #pragma unroll
        for (int i=0;i<4;i++){
            int idx = t + i*512;
            int r = idx >> 4, c8 = (idx & 15) << 3;
            *(uint4*)(sE + r*G2_STR + c8) = *(const uint4*)(src + (size_t)r*FOUT + c8);
        }
        const uint4* sw = (const uint4*)(g_W1h + (size_t)nt*128*G2_STR);
        uint4* dw = (uint4*)sB;
        #pragma unroll
        for (int i=0;i<5;i++){
            int idx = t + i*512;
            if (idx < 128*G2_STR/8) dw[idx] = sw[idx];
        }
    }
    __syncthreads();

    wmma::fragment<wmma::accumulator,16,16,16,float> acc[2][2];
    #pragma unroll
    for (int i=0;i<2;i++)
        #pragma unroll
        for (int j=0;j<2;j++) wmma::fill_fragment(acc[i][j], 0.0f);

    #pragma unroll
    for (int kk=0; kk<8; kk++){
        wmma::fragment<wmma::matrix_a,16,16,16,__half,wmma::row_major> af[2];
        wmma::fragment<wmma::matrix_b,16,16,16,__half,wmma::row_major> bf[2];
        #pragma unroll
        for (int i=0;i<2;i++)
            wmma::load_matrix_sync(af[i], sE + (wm*32 + i*16)*G2_STR + kk*16, G2_STR);
        #pragma unroll
        for (int j=0;j<2;j++)
            wmma::load_matrix_sync(bf[j], sB + (kk*16)*G2_STR + wn*32 + j*16, G2_STR);
        #pragma unroll
        for (int i=0;i<2;i++)
            #pragma unroll
            for (int j=0;j<2;j++)
                wmma::mma_sync(acc[i][j], af[i], bf[j], acc[i][j]);
    }
    __syncthreads();

    float* so = (float*)smem_raw;    // 128x128 f32 = 64KB (fits in 69632)
    #pragma unroll
    for (int i=0;i<2;i++)
        #pragma unroll
        for (int j=0;j<2;j++)
            wmma::store_matrix_sync(so + (wm*32+i*16)*128 + wn*32 + j*16, acc[i][j], 128, wmma::mem_row_major);
    __syncthreads();

    const bool isA = ((nt & 1) == 0);
    const float* bias = b1 + (nt >> 1) * 128;
    #pragma unroll
    for (int i=0;i<8;i++){
        int idx = t + i*512;                     // float4 index over 128x128
        int r = idx >> 5;
        int c = (idx & 31) << 2;
        float4 v = *(float4*)(so + r*128 + c);
        if (isA){
            float4 bb = *(const float4*)(bias + c);
            v.x += bb.x; v.y += bb.y; v.z += bb.z; v.w += bb.w;
        }
        *(float4*)(g_AC + (size_t)(m0+r)*NCAT + nt*128 + c) = v;
    }
}

// ---------------------------------------------------------------------------
// Combine: warp per (b,h). A rows in ten NAMED float4 registers; k plain loop.
// adj[b,h,j,i] = S[i, j+(j>=i)]; rows 9.. zeroed. Grid 1024 x 256 (8 warps).
// ---------------------------------------------------------------------------
__global__ void __launch_bounds__(256) combine_kernel(const float* __restrict__ W2,
                                                      const float* __restrict__ b2,
                                                      float* __restrict__ out)
{
    const int warp = threadIdx.x >> 5;
    const int lane = threadIdx.x & 31;
    const int unit = blockIdx.x * 8 + warp;      // 0..8191
    const int b = unit >> 3, h = unit & 7;

    const float4 w4  = *(const float4*)(W2 + h*HID + lane*4);
    const float  b2h = b2[h];
    const float* base = g_AC + (size_t)b*NNODE*NCAT + h*256 + lane*4;

    float4 a0 = *(const float4*)(base + 0*NCAT);
    float4 a1 = *(const float4*)(base + 1*NCAT);
    float4 a2 = *(const float4*)(base + 2*NCAT);
    float4 a3 = *(const float4*)(base + 3*NCAT);
    float4 a4 = *(const float4*)(base + 4*NCAT);
    float4 a5 = *(const float4*)(base + 5*NCAT);
    float4 a6 = *(const float4*)(base + 6*NCAT);
    float4 a7 = *(const float4*)(base + 7*NCAT);
    float4 a8 = *(const float4*)(base + 8*NCAT);
    float4 a9 = *(const float4*)(base + 9*NCAT);

    float* o = out + (size_t)(b*NH + h) * 100;

#define GPN_PAIR(ii, areg)                                                     \
    {                                                                          \
        float vx = areg.x + c4.x;  vx = (vx > 0.f) ? vx : 0.2f*vx;             \
        float vy = areg.y + c4.y;  vy = (vy > 0.f) ? vy : 0.2f*vy;             \
        float vz = areg.z + c4.z;  vz = (vz > 0.f) ? vz : 0.2f*vz;             \
        float vw = areg.w + c4.w;  vw = (vw > 0.f) ? vw : 0.2f*vw;             \
        float s = vx*w4.x + vy*w4.y + vz*w4.z + vw*w4.w;                       \
        s += __shfl_xor_sync(0xffffffffu, s, 16);                              \
        s += __shfl_xor_sync(0xffffffffu, s, 8);                               \
        s += __shfl_xor_sync(0xffffffffu, s, 4);                               \
        s += __shfl_xor_sync(0xffffffffu, s, 2);                               \
        s += __shfl_xor_sync(0xffffffffu, s, 1);                               \
        if (lane == 0 && k != (ii)){                                           \
            const int jj = (k < (ii)) ? k : (k - 1);                           \
            o[jj*10 + (ii)] = s + b2h;                                         \
        }                                                                      \
    }

    for (int k = 0; k < 10; k++){
        float4 c4 = *(const float4*)(base + (size_t)k*NCAT + 128);
        GPN_PAIR(0, a0)
        GPN_PAIR(1, a1)
        GPN_PAIR(2, a2)
        GPN_PAIR(3, a3)
        GPN_PAIR(4, a4)
        GPN_PAIR(5, a5)
        GPN_PAIR(6, a6)
        GPN_PAIR(7, a7)
        GPN_PAIR(8, a8)
        GPN_PAIR(9, a9)
    }
#undef GPN_PAIR

    if (lane < 10) o[90 + lane] = 0.0f;
}

// ---------------------------------------------------------------------------
extern "C" void kernel_launch(void* const* d_in, const int* in_sizes, int n_in,
                              void* d_out, int out_size)
{
    const float* X  = (const float*)d_in[0];
    const float* Wp = (const float*)d_in[2];
    const float* bp = (const float*)d_in[3];
    const float* W1 = (const float*)d_in[4];
    const float* b1 = (const float*)d_in[5];
    const float* W2 = (const float*)d_in[6];
    const float* b2 = (const float*)d_in[7];
    float* out = (float*)d_out;

    cudaFuncSetAttribute(gemm1_kernel, cudaFuncAttributeMaxDynamicSharedMemorySize, G1_SMEM);
    cudaFuncSetAttribute(gemm2_kernel, cudaFuncAttributeMaxDynamicSharedMemorySize, G2_SMEM);

    w1pack_kernel<<<(NH*2*128*136 + 255)/256, 256>>>(W1);
    gemm1_kernel<<<M1/64, 256, G1_SMEM>>>(X, Wp, bp);
    gemm2_kernel<<<dim3(M1/128, 16), 512, G2_SMEM>>>(b1);
    combine_kernel<<<1024, 256>>>(W2, b2, out);
    (void)in_sizes; (void)n_in; (void)out_size;
}

// round 14
// speedup vs baseline: 1.2155x; 1.2155x over previous
#include <cuda_runtime.h>
#include <cuda_fp16.h>
#include <mma.h>
#include <cstdint>

using namespace nvcuda;

static constexpr int B_    = 1024;
static constexpr int NNODE = 10;
static constexpr int FIN   = 2048;
static constexpr int FOUT  = 128;
static constexpr int NH    = 8;
static constexpr int HID   = 128;
static constexpr int M1    = B_ * NNODE;      // 10240 rows
static constexpr int NCAT  = 2048;            // 8 heads * 2 halves * 128

// Scratch (device globals; referenced ONLY in device code — never as host-side
// kernel arguments, which caused the R8-R11 guard trips).
__device__ __half g_emb[(size_t)M1 * FOUT];                 // 2.6 MB
__device__ __half g_AC [(size_t)M1 * NCAT];                 // 42 MB f16 (L2-resident)

// ---------------------------------------------------------------------------
// GEMM1: emb[10240,128] = X[10240,2048] @ Wp[2048,128] + bp   (f16 in, f32 acc)
// Unchanged (R6/R7/R13 proven, ~49us). Block 64x128, BK=64, 8 warps, dbl buffer.
// ---------------------------------------------------------------------------
static constexpr int G1_SA_STR  = 72;
static constexpr int G1_SB_STR  = 136;
static constexpr int G1_SA_BUF  = 64 * G1_SA_STR;
static constexpr int G1_SB_BUF  = 64 * G1_SB_STR;
static constexpr int G1_SMEM    = 2*G1_SA_BUF*2 + 2*G1_SB_BUF*2;  // 53248 B

__global__ void __launch_bounds__(256) gemm1_kernel(const float* __restrict__ X,
                                                    const float* __restrict__ Wp,
                                                    const float* __restrict__ bp)
{
    extern __shared__ __align__(16) char smem_raw[];
    __half* sA = (__half*)smem_raw;
    __half* sB = (__half*)(smem_raw + 2*G1_SA_BUF*2);

    const int t    = threadIdx.x;
    const int m0   = blockIdx.x * 64;
    const int warp = t >> 5;
    const int wm   = warp >> 2;
    const int wn   = warp & 3;

    wmma::fragment<wmma::accumulator,16,16,16,float> acc[2][2];
    #pragma unroll
    for (int i=0;i<2;i++)
        #pragma unroll
        for (int j=0;j<2;j++) wmma::fill_fragment(acc[i][j], 0.0f);

    float4 pa[4], pb[8];
    #pragma unroll
    for (int i=0;i<4;i++){ int idx=t+i*256; int r=idx>>4, c=(idx&15)<<2;
        pa[i] = *(const float4*)(X + (size_t)(m0+r)*FIN + c); }
    #pragma unroll
    for (int i=0;i<8;i++){ int idx=t+i*256; int r=idx>>5, c=(idx&31)<<2;
        pb[i] = *(const float4*)(Wp + (size_t)r*FOUT + c); }

    auto store_tiles = [&](int buf){
        __half* a = sA + buf*G1_SA_BUF;
        __half* b = sB + buf*G1_SB_BUF;
        #pragma unroll
        for (int i=0;i<4;i++){ int idx=t+i*256; int r=idx>>4, c=(idx&15)<<2;
            __half2 h0 = __floats2half2_rn(pa[i].x, pa[i].y);
            __half2 h1 = __floats2half2_rn(pa[i].z, pa[i].w);
            __half2* p = (__half2*)(a + r*G1_SA_STR + c);
            p[0] = h0; p[1] = h1; }
        #pragma unroll
        for (int i=0;i<8;i++){ int idx=t+i*256; int r=idx>>5, c=(idx&31)<<2;
            __half2 h0 = __floats2half2_rn(pb[i].x, pb[i].y);
            __half2 h1 = __floats2half2_rn(pb[i].z, pb[i].w);
            __half2* p = (__half2*)(b + r*G1_SB_STR + c);
            p[0] = h0; p[1] = h1; }
    };

    store_tiles(0);
    __syncthreads();

    int buf = 0;
    for (int k0 = 0; k0 < FIN; k0 += 64)
    {
        const int kn = k0 + 64;
        if (kn < FIN){
            #pragma unroll
            for (int i=0;i<4;i++){ int idx=t+i*256; int r=idx>>4, c=(idx&15)<<2;
                pa[i] = *(const float4*)(X + (size_t)(m0+r)*FIN + kn + c); }
            #pragma unroll
            for (int i=0;i<8;i++){ int idx=t+i*256; int r=idx>>5, c=(idx&31)<<2;
                pb[i] = *(const float4*)(Wp + (size_t)(kn+r)*FOUT + c); }
        }

        const __half* a = sA + buf*G1_SA_BUF;
        const __half* b = sB + buf*G1_SB_BUF;
        #pragma unroll
        for (int kk=0; kk<4; kk++){
            wmma::fragment<wmma::matrix_a,16,16,16,__half,wmma::row_major> af[2];
            wmma::fragment<wmma::matrix_b,16,16,16,__half,wmma::row_major> bf[2];
            #pragma unroll
            for (int i=0;i<2;i++)
                wmma::load_matrix_sync(af[i], a + (wm*32 + i*16)*G1_SA_STR + kk*16, G1_SA_STR);
            #pragma unroll
            for (int j=0;j<2;j++)
                wmma::load_matrix_sync(bf[j], b + (kk*16)*G1_SB_STR + wn*32 + j*16, G1_SB_STR);
            #pragma unroll
            for (int i=0;i<2;i++)
                #pragma unroll
                for (int j=0;j<2;j++)
                    wmma::mma_sync(acc[i][j], af[i], bf[j], acc[i][j]);
        }

        if (kn < FIN) store_tiles(buf ^ 1);
        __syncthreads();
        buf ^= 1;
    }

    float* se = (float*)smem_raw;
    #pragma unroll
    for (int i=0;i<2;i++)
        #pragma unroll
        for (int j=0;j<2;j++)
            wmma::store_matrix_sync(se + (wm*32+i*16)*128 + wn*32 + j*16, acc[i][j], 128, wmma::mem_row_major);
    __syncthreads();
    #pragma unroll
    for (int i=0;i<8;i++){
        int idx = t + i*256;
        int r = idx >> 5;
        int c = (idx & 31) << 2;
        float4 v  = *(float4*)(se + r*128 + c);
        float4 bb = *(const float4*)(bp + c);
        __half2 h0 = __floats2half2_rn(v.x + bb.x, v.y + bb.y);
        __half2 h1 = __floats2half2_rn(v.z + bb.z, v.w + bb.w);
        __half2* p = (__half2*)(g_emb + (size_t)(m0+r)*FOUT + c);
        p[0] = h0; p[1] = h1;
    }
}

// ---------------------------------------------------------------------------
// GEMM2: g_AC[10240,2048] (f16) = emb @ Wcat (+ b1 on A-halves).
// W1 slab nt staged DIRECTLY from f32 (L2-resident, 80 blocks reuse each slab)
// with inline f32->f16 conversion — no pack kernel.
// Block 128x128, 512 threads, 16 warps (warp tile 32x32).
// smem: sE f16[128][136] + sB f16[128][136] = 69632 B.
// ---------------------------------------------------------------------------
static constexpr int G2_STR  = 136;
static constexpr int G2_SMEM = 2 * 128 * G2_STR * 2;   // 69632 B

__global__ void __launch_bounds__(512) gemm2_kernel(const float* __restrict__ W1,
                                                    const float* __restrict__ b1)
{
    extern __shared__ __align__(16) char smem_raw[];
    __half* sE = (__half*)smem_raw;                       // [128][136]
    __half* sB = (__half*)(smem_raw + 128*G2_STR*2);      // [128][136]

    const int t    = threadIdx.x;
    const int m0   = blockIdx.x * 128;
    const int nt   = blockIdx.y;                          // 0..15 = h*2+s
    const int warp = t >> 5;
    const int wm   = warp & 3;       // row tile of 32
    const int wn   = warp >> 2;      // col tile of 32

    // stage emb rows (raw f16 copy) + W1 slab (f32 -> f16 inline)
    {
        const __half* src = g_emb + (size_t)m0*FOUT;
        #pragma unroll
        for (int i=0;i<4;i++){
            int idx = t + i*512;
            int r = idx >> 4, c8 = (idx & 15) << 3;
            *(uint4*)(sE + r*G2_STR + c8) = *(const uint4*)(src + (size_t)r*FOUT + c8);
        }
        const float* srcW = W1 + (size_t)nt * (128*HID);  // rows = k, 128x128 f32
        #pragma unroll
        for (int i=0;i<8;i++){
            int idx = t + i*512;                          // 4096 float4
            int r = idx >> 5, c = (idx & 31) << 2;
            float4 v = *(const float4*)(srcW + (size_t)r*HID + c);
            __half2* p = (__half2*)(sB + r*G2_STR + c);
            p[0] = __floats2half2_rn(v.x, v.y);
            p[1] = __floats2half2_rn(v.z, v.w);
        }
    }
    __syncthreads();

    wmma::fragment<wmma::accumulator,16,16,16,float> acc[2][2];
    #pragma unroll
    for (int i=0;i<2;i++)
        #pragma unroll
        for (int j=0;j<2;j++) wmma::fill_fragment(acc[i][j], 0.0f);

    #pragma unroll
    for (int kk=0; kk<8; kk++){
        wmma::fragment<wmma::matrix_a,16,16,16,__half,wmma::row_major> af[2];
        wmma::fragment<wmma::matrix_b,16,16,16,__half,wmma::row_major> bf[2];
        #pragma unroll
        for (int i=0;i<2;i++)
            wmma::load_matrix_sync(af[i], sE + (wm*32 + i*16)*G2_STR + kk*16, G2_STR);
        #pragma unroll
        for (int j=0;j<2;j++)
            wmma::load_matrix_sync(bf[j], sB + (kk*16)*G2_STR + wn*32 + j*16, G2_STR);
        #pragma unroll
        for (int i=0;i<2;i++)
            #pragma unroll
            for (int j=0;j<2;j++)
                wmma::mma_sync(acc[i][j], af[i], bf[j], acc[i][j]);
    }
    __syncthreads();

    float* so = (float*)smem_raw;    // 128x128 f32 = 64KB (fits in 69632)
    #pragma unroll
    for (int i=0;i<2;i++)
        #pragma unroll
        for (int j=0;j<2;j++)
            wmma::store_matrix_sync(so + (wm*32+i*16)*128 + wn*32 + j*16, acc[i][j], 128, wmma::mem_row_major);
    __syncthreads();

    const bool isA = ((nt & 1) == 0);
    const float* bias = b1 + (nt >> 1) * 128;
    #pragma unroll
    for (int i=0;i<4;i++){
        int idx = t + i*512;                     // 2048 chunks of 8 floats
        int r  = idx >> 4;
        int c8 = (idx & 15) << 3;
        float4 v0 = *(float4*)(so + r*128 + c8);
        float4 v1 = *(float4*)(so + r*128 + c8 + 4);
        if (isA){
            float4 b0 = *(const float4*)(bias + c8);
            float4 b1v = *(const float4*)(bias + c8 + 4);
            v0.x += b0.x; v0.y += b0.y; v0.z += b0.z; v0.w += b0.w;
            v1.x += b1v.x; v1.y += b1v.y; v1.z += b1v.z; v1.w += b1v.w;
        }
        __half2 h[4];
        h[0] = __floats2half2_rn(v0.x, v0.y);
        h[1] = __floats2half2_rn(v0.z, v0.w);
        h[2] = __floats2half2_rn(v1.x, v1.y);
        h[3] = __floats2half2_rn(v1.z, v1.w);
        *(uint4*)(g_AC + (size_t)(m0+r)*NCAT + nt*128 + c8) = *(uint4*)h;
    }
}

// ---------------------------------------------------------------------------
// Combine: warp per (b,h). ALL 20 rows (10 A as converted float4, 10 C as raw
// uint2 halves) prefetched into NAMED registers (MLP=20, no demotable arrays).
// Fully unrolled compile-time 10x10 body.
// adj[b,h,j,i] = S[i, j+(j>=i)]; rows 9.. zeroed. Grid 1024 x 256 (8 warps).
// ---------------------------------------------------------------------------
__global__ void __launch_bounds__(256) combine_kernel(const float* __restrict__ W2,
                                                      const float* __restrict__ b2,
                                                      float* __restrict__ out)
{
    const int warp = threadIdx.x >> 5;
    const int lane = threadIdx.x & 31;
    const int unit = blockIdx.x * 8 + warp;      // 0..8191
    const int b = unit >> 3, h = unit & 7;

    const float4 w4  = *(const float4*)(W2 + h*HID + lane*4);
    const float  b2h = b2[h];
    const __half* base = g_AC + (size_t)b*NNODE*NCAT + h*256 + lane*4;

#define GPN_LDA(reg, ii)                                                       \
    float4 reg;                                                                \
    {                                                                          \
        uint2 r_ = *(const uint2*)(base + (ii)*NCAT);                          \
        float2 f0 = __half22float2(*(__half2*)&r_.x);                          \
        float2 f1 = __half22float2(*(__half2*)&r_.y);                          \
        reg = make_float4(f0.x, f0.y, f1.x, f1.y);                             \
    }
#define GPN_LDC(reg, kk)                                                       \
    uint2 reg = *(const uint2*)(base + (kk)*NCAT + 128);

    GPN_LDC(c0_, 0) GPN_LDC(c1_, 1) GPN_LDC(c2_, 2) GPN_LDC(c3_, 3) GPN_LDC(c4_, 4)
    GPN_LDC(c5_, 5) GPN_LDC(c6_, 6) GPN_LDC(c7_, 7) GPN_LDC(c8_, 8) GPN_LDC(c9_, 9)
    GPN_LDA(a0, 0) GPN_LDA(a1, 1) GPN_LDA(a2, 2) GPN_LDA(a3, 3) GPN_LDA(a4, 4)
    GPN_LDA(a5, 5) GPN_LDA(a6, 6) GPN_LDA(a7, 7) GPN_LDA(a8, 8) GPN_LDA(a9, 9)

    float* o = out + (size_t)(b*NH + h) * 100;

#define GPN_PAIR(kk, ii, areg)                                                 \
    if ((kk) != (ii)){                                                         \
        float vx = areg.x + c4v.x;  vx = (vx > 0.f) ? vx : 0.2f*vx;            \
        float vy = areg.y + c4v.y;  vy = (vy > 0.f) ? vy : 0.2f*vy;            \
        float vz = areg.z + c4v.z;  vz = (vz > 0.f) ? vz : 0.2f*vz;            \
        float vw = areg.w + c4v.w;  vw = (vw > 0.f) ? vw : 0.2f*vw;            \
        float s = vx*w4.x + vy*w4.y + vz*w4.z + vw*w4.w;                       \
        s += __shfl_xor_sync(0xffffffffu, s, 16);                              \
        s += __shfl_xor_sync(0xffffffffu, s, 8);                               \
        s += __shfl_xor_sync(0xffffffffu, s, 4);                               \
        s += __shfl_xor_sync(0xffffffffu, s, 2);                               \
        s += __shfl_xor_sync(0xffffffffu, s, 1);                               \
        if (lane == 0){                                                        \
            const int jj = ((kk) < (ii)) ? (kk) : ((kk) - 1);                  \
            o[jj*10 + (ii)] = s + b2h;                                         \
        }                                                                      \
    }

#define GPN_KROW(kk, creg)                                                     \
    {                                                                          \
        float2 f0 = __half22float2(*(__half2*)&creg.x);                        \
        float2 f1 = __half22float2(*(__half2*)&creg.y);                        \
        float4 c4v = make_float4(f0.x, f0.y, f1.x, f1.y);                      \
        GPN_PAIR(kk, 0, a0) GPN_PAIR(kk, 1, a1) GPN_PAIR(kk, 2, a2)            \
        GPN_PAIR(kk, 3, a3) GPN_PAIR(kk, 4, a4) GPN_PAIR(kk, 5, a5)            \
        GPN_PAIR(kk, 6, a6) GPN_PAIR(kk, 7, a7) GPN_PAIR(kk, 8, a8)            \
        GPN_PAIR(kk, 9, a9)                                                    \
    }

    GPN_KROW(0, c0_) GPN_KROW(1, c1_) GPN_KROW(2, c2_) GPN_KROW(3, c3_)
    GPN_KROW(4, c4_) GPN_KROW(5, c5_) GPN_KROW(6, c6_) GPN_KROW(7, c7_)
    GPN_KROW(8, c8_) GPN_KROW(9, c9_)

#undef GPN_KROW
#undef GPN_PAIR
#undef GPN_LDC
#undef GPN_LDA

    if (lane < 10) o[90 + lane] = 0.0f;
}

// ---------------------------------------------------------------------------
extern "C" void kernel_launch(void* const* d_in, const int* in_sizes, int n_in,
                              void* d_out, int out_size)
{
    const float* X  = (const float*)d_in[0];
    const float* Wp = (const float*)d_in[2];
    const float* bp = (const float*)d_in[3];
    const float* W1 = (const float*)d_in[4];
    const float* b1 = (const float*)d_in[5];
    const float* W2 = (const float*)d_in[6];
    const float* b2 = (const float*)d_in[7];
    float* out = (float*)d_out;

    cudaFuncSetAttribute(gemm1_kernel, cudaFuncAttributeMaxDynamicSharedMemorySize, G1_SMEM);
    cudaFuncSetAttribute(gemm2_kernel, cudaFuncAttributeMaxDynamicSharedMemorySize, G2_SMEM);

    gemm1_kernel<<<M1/64, 256, G1_SMEM>>>(X, Wp, bp);
    gemm2_kernel<<<dim3(M1/128, 16), 512, G2_SMEM>>>(W1, b1);
    combine_kernel<<<1024, 256>>>(W2, b2, out);
    (void)in_sizes; (void)n_in; (void)out_size;
}